// round 16
// baseline (speedup 1.0000x reference)
#include <cuda_runtime.h>
#include <math_constants.h>

#define NB 64
#define NC 1000
#define HW 196
#define NF4 49
#define GY 25                             // blocks per batch
#define CPB (NC / GY)                     // 40 classes per block -> 5 rows/warp
#define NROW 5                            // rows per warp (compile-time)
#define C4L2E 5.770780163555852f          // 4 * log2(e)
#define RC4L2E 0.17328679513998632f       // 1 / C4L2E
#define LN2   0.6931471805599453f
#define L2E   1.4426950408889634f
#define CLIP2 (-19.931568569324174f)      // log2(1e-6)
#define DEADB (-24000.0f)                 // u bias for dead lane-slots: 2^u == 0

// hierarchical partials (no per-class arrays)
__device__ float g_bmx[NB * GY];
__device__ float g_bse[NB * GY];
__device__ float g_bsa[NB * GY];
__device__ float g_bkp[NB * GY];
__device__ float g_al[NB];                // abl[label] scalar
__device__ float g_ace[NB];
__device__ float g_kld[NB];
__device__ int   g_bcnt[NB];              // zero-init; reset by final block
__device__ int   g_done = 0;

__device__ __forceinline__ float ex2f(float x) {
    float r; asm("ex2.approx.f32 %0, %1;" : "=f"(r) : "f"(x)); return r;
}
__device__ __forceinline__ float warpSum(float v) {
#pragma unroll
    for (int o = 16; o; o >>= 1) v += __shfl_xor_sync(0xffffffffu, v, o);
    return v;
}
__device__ __forceinline__ float warpMax(float v) {
#pragma unroll
    for (int o = 16; o; o >>= 1) v = fmaxf(v, __shfl_xor_sync(0xffffffffu, v, o));
    return v;
}

// ---------------------------------------------------------------------------
// Fused kernel. grid=(NB, GY), block=256 (8 warps; warp w owns rows w+8i,
// i=0..4). Fully unrolled row loop, indexed addressing, NO cross-row serial
// chains. Single change vs R15 winner: __launch_bounds__(256, 6) caps regs
// at 42 -> 6 blocks/SM (48 warps, 75% theoretical occupancy); testing where
// the occupancy-vs-MLP frontier bends.
// ---------------------------------------------------------------------------
__global__ __launch_bounds__(256, 6) void k1(const float* __restrict__ cams,
                                             const int* __restrict__ y0,
                                             const int* __restrict__ labels,
                                             float* __restrict__ out) {
    __shared__ float4 s_tn4[NF4];   // tnu = -C4L2E * target row
    __shared__ float4 s_f4[NF4];    // f2 = 2 * fg mask
    __shared__ float sh_mx[8];
    __shared__ float sh_se[8];
    __shared__ float sh_sa[8];
    __shared__ float sh_kp[8];
    __shared__ int s_flag;

    const int b = blockIdx.x;
    const int tid = threadIdx.x;
    const int label = __ldg(labels + b);
    const float* base = cams + (size_t)b * NC * HW;

    if (tid < HW) {
        ((float*)s_tn4)[tid] = -C4L2E * __ldg(base + (size_t)label * HW + tid);
        ((float*)s_f4)[tid]  = 2.0f * (float)__ldg(y0 + b * HW + tid);
    }
    __syncthreads();

    const int warp = tid >> 5;
    const int lane = tid & 31;
    const bool live = lane < (NF4 - 32);
    const int idx2 = 32 + (live ? lane : 16);     // clamped (slot 48 valid)
    const float m1 = live ? 1.0f : 0.0f;

    const float4 tnu0 = s_tn4[lane];
    const float4 f0   = s_f4[lane];               // f2 values
    float4 tnu1, f1;
    if (live) { tnu1 = s_tn4[idx2]; f1 = s_f4[idx2]; }
    else {
        tnu1 = make_float4(DEADB, DEADB, DEADB, DEADB);
        f1   = make_float4(0.f, 0.f, 0.f, 0.f);
    }

    // row-invariant fg count: n1 = 0.5 * sum(f2)
    float n1 = 0.5f * ((f0.x + f0.y) + (f0.z + f0.w) +
                       (f1.x + f1.y) + (f1.z + f1.w));
    n1 = warpSum(n1);

    const int c0 = blockIdx.y * CPB;
    float kacc = 0.f;      // per-lane, across rows
    float L2sum = 0.f;     // lane-uniform
    float abl[NROW];       // per-row abl values (register array, full unroll)

#pragma unroll
    for (int i = 0; i < NROW; i++) {
        const int cl = warp + 8 * i;              // < CPB always
        const float4* row4 = (const float4*)(base + (size_t)(c0 + cl) * HW);
        const float4 a0 = __ldg(row4 + lane);
        const float4 a1 = __ldg(row4 + idx2);

        float u[8];
        float den = 0.f, sabs = 0.f, sfp = 0.f;

        u[0] = fmaf(C4L2E, a0.x, tnu0.x); den += ex2f(u[0]);
        sabs += fabsf(u[0]); sfp = fmaf(f0.x, fmaxf(u[0], 0.f), sfp);
        u[1] = fmaf(C4L2E, a0.y, tnu0.y); den += ex2f(u[1]);
        sabs += fabsf(u[1]); sfp = fmaf(f0.y, fmaxf(u[1], 0.f), sfp);
        u[2] = fmaf(C4L2E, a0.z, tnu0.z); den += ex2f(u[2]);
        sabs += fabsf(u[2]); sfp = fmaf(f0.z, fmaxf(u[2], 0.f), sfp);
        u[3] = fmaf(C4L2E, a0.w, tnu0.w); den += ex2f(u[3]);
        sabs += fabsf(u[3]); sfp = fmaf(f0.w, fmaxf(u[3], 0.f), sfp);

        u[4] = fmaf(C4L2E, a1.x, tnu1.x); den += ex2f(u[4]);
        sabs = fmaf(m1, fabsf(u[4]), sabs); sfp = fmaf(f1.x, fmaxf(u[4], 0.f), sfp);
        u[5] = fmaf(C4L2E, a1.y, tnu1.y); den += ex2f(u[5]);
        sabs = fmaf(m1, fabsf(u[5]), sabs); sfp = fmaf(f1.y, fmaxf(u[5], 0.f), sfp);
        u[6] = fmaf(C4L2E, a1.z, tnu1.z); den += ex2f(u[6]);
        sabs = fmaf(m1, fabsf(u[6]), sabs); sfp = fmaf(f1.z, fmaxf(u[6], 0.f), sfp);
        u[7] = fmaf(C4L2E, a1.w, tnu1.w); den += ex2f(u[7]);
        sabs = fmaf(m1, fabsf(u[7]), sabs); sfp = fmaf(f1.w, fmaxf(u[7], 0.f), sfp);

        den = warpSum(den);
        const float L2 = __log2f(den);
        const float Lc = L2 + CLIP2;
        L2sum += L2;

        kacc = fmaf(f0.x, fmaxf(u[0], Lc), kacc);
        kacc = fmaf(f0.y, fmaxf(u[1], Lc), kacc);
        kacc = fmaf(f0.z, fmaxf(u[2], Lc), kacc);
        kacc = fmaf(f0.w, fmaxf(u[3], Lc), kacc);
        kacc = fmaf(f1.x, fmaxf(u[4], Lc), kacc);
        kacc = fmaf(f1.y, fmaxf(u[5], Lc), kacc);
        kacc = fmaf(f1.z, fmaxf(u[6], Lc), kacc);
        kacc = fmaf(f1.w, fmaxf(u[7], Lc), kacc);

        const float s1 = warpSum(sabs - sfp);
        abl[i] = s1 * RC4L2E;

        if (lane == 0 && (c0 + cl) == label) g_al[b] = abl[i];
    }

    // lse + sum over the 5 per-row abl values (once, after the loop)
    float mxw = abl[0];
#pragma unroll
    for (int i = 1; i < NROW; i++) mxw = fmaxf(mxw, abl[i]);
    float sew = 0.f, saw = 0.f;
#pragma unroll
    for (int i = 0; i < NROW; i++) {
        sew += ex2f((abl[i] - mxw) * L2E);
        saw += abl[i];
    }

    kacc = warpSum(kacc);
    if (lane == 0) {
        sh_mx[warp] = mxw;
        sh_se[warp] = sew;
        sh_sa[warp] = saw;
        sh_kp[warp] = -LN2 * (0.5f * kacc - n1 * L2sum);
    }
    __syncthreads();

    // warp 0: combine 8 warp-partials -> 4 scalars for this block
    if (warp == 0) {
        const bool v = lane < 8;
        float m  = v ? sh_mx[lane] : -CUDART_INF_F;
        float se = v ? sh_se[lane] : 0.f;
        float sa = v ? sh_sa[lane] : 0.f;
        float kp = v ? sh_kp[lane] : 0.f;
        const float M = warpMax(m);
        se = se * ex2f((m - M) * L2E);            // -inf lanes -> 0
        se = warpSum(se); sa = warpSum(sa); kp = warpSum(kp);
        if (lane == 0) {
            const int gi = b * GY + blockIdx.y;
            g_bmx[gi] = M; g_bse[gi] = se; g_bsa[gi] = sa; g_bkp[gi] = kp;
        }
    }
    __syncthreads();

    // ---------------- Phase B election: last block of this batch ------------
    if (tid == 0) {
        __threadfence();                        // release this block's partials
        s_flag = (atomicAdd(&g_bcnt[b], 1) == GY - 1);
    }
    __syncthreads();
    if (!s_flag || warp != 0) return;

    // ---------------- Phase B: combine 25 block-partials (warp 0 only) ------
    __threadfence();                            // acquire peers' partials
    {
        const bool v = lane < GY;
        const int gi = b * GY + (v ? lane : 0);
        float m  = v ? g_bmx[gi] : -CUDART_INF_F;
        float se = v ? g_bse[gi] : 0.f;
        float sa = v ? g_bsa[gi] : 0.f;
        float kp = v ? g_bkp[gi] : 0.f;
        const float bmax = warpMax(m);
        se = se * ex2f((m - bmax) * L2E);
        se = warpSum(se); sa = warpSum(sa); kp = warpSum(kp);

        int lastg = 0;
        if (lane == 0) {
            const float L = __logf(se);
            const float al = g_al[b];
            const float ace = -(0.9f * (al - bmax - L) +
                                1e-4f * (sa - (float)NC * (bmax + L)));
            float p1 = 0.f;
            if (n1 > 0.f) p1 = 1.f / (n1 + ((float)HW - n1) * __expf(-10.f));
            g_ace[b] = ace;
            g_kld[b] = p1 * kp;
            __threadfence();
            lastg = (atomicAdd(&g_done, 1) == NB - 1);
        }
        lastg = __shfl_sync(0xffffffffu, lastg, 0);
        if (!lastg) return;
    }

    // ---------------- Phase C: final 64 -> 1 + counter reset ----------------
    __threadfence();                            // acquire all g_ace/g_kld
    {
        float a = g_ace[lane] + g_ace[lane + 32];
        float k = g_kld[lane] + g_kld[lane + 32];
        a = warpSum(a);
        k = warpSum(k);
        g_bcnt[lane] = 0;
        g_bcnt[lane + 32] = 0;
        if (lane == 0) {
            out[0] = (a + 0.5f * k) * (1.0f / NB);
            g_done = 0;
        }
    }
}

extern "C" void kernel_launch(void* const* d_in, const int* in_sizes, int n_in,
                              void* d_out, int out_size) {
    const float* cams  = (const float*)d_in[0];
    const int* y0      = (const int*)d_in[1];
    const int* labels  = (const int*)d_in[2];
    float* out = (float*)d_out;

    k1<<<dim3(NB, GY), 256>>>(cams, y0, labels, out);
}